// round 8
// baseline (speedup 1.0000x reference)
#include <cuda_runtime.h>
#include <cstdint>

#define MAXB 8
#define MAXN 2048

// ---------------- scratch ----------------
__device__ float g_embnP[MAXB * MAXN * 64];   // emb_n, node-major, phi f (fp32, knn)
__device__ float g_Ep   [MAXB * MAXN * 64];   // emb,   node-major, phi f
__device__ float g_EjF  [MAXB * MAXN * 64];   // emb  gemm1-B fragments, tile-major
__device__ float g_EnF  [MAXB * MAXN * 64];   // embn gemm2-B fragments, tile-major
__device__ float g_sq   [MAXB * MAXN];
__device__ float g_deg  [MAXB * MAXN];
__device__ float g_opadjP[MAXB * MAXN * 64];
__device__ float g_part [MAXB * 8 * 128];
__device__ float g_stats[MAXB * 128];

__device__ __forceinline__ int phi(int k) {
    int r = k & 7;
    return (k & ~7) | (((r & 3) << 1) | (r >> 2));
}

__device__ __forceinline__ uint32_t f2tf(float x) {
    uint32_t r;
    asm("cvt.rna.tf32.f32 %0, %1;" : "=r"(r) : "f"(x));
    return r;
}

__device__ __forceinline__ void split_tf(float v, uint32_t& hi, uint32_t& lo) {
    hi = f2tf(v);
    lo = f2tf(v - __uint_as_float(hi));
}

__device__ __forceinline__ void cpa16(uint32_t saddr, const void* gaddr) {
    asm volatile("cp.async.cg.shared.global [%0], [%1], 16;\n"
                 :: "r"(saddr), "l"(gaddr));
}

#define MMA_TF32(d, a0, a1, a2, a3, b0, b1)                                  \
    asm volatile(                                                            \
        "mma.sync.aligned.m16n8k8.row.col.f32.tf32.tf32.f32 "                \
        "{%0,%1,%2,%3}, {%4,%5,%6,%7}, {%8,%9}, {%0,%1,%2,%3};\n"            \
        : "+f"(d[0]), "+f"(d[1]), "+f"(d[2]), "+f"(d[3])                     \
        : "r"(a0), "r"(a1), "r"(a2), "r"(a3), "r"(b0), "r"(b1))

// ---------------- Kernel 1a: partial sums (grid B x 8) ----------------
__global__ __launch_bounds__(256) void kstat1(const float* __restrict__ emb, int N)
{
    __shared__ float ssum[4][64], ssq[4][64];
    const int b = blockIdx.x, slice = blockIdx.y;
    const int t = threadIdx.x, f = t & 63, g = t >> 6;
    const int r0 = slice * (N / 8), r1 = r0 + N / 8;
    const float* E = emb + (size_t)b * N * 64;

    float s = 0.f, q = 0.f;
    for (int i = r0 + g; i < r1; i += 4) {
        float v = E[(size_t)i * 64 + f];
        s += v; q += v * v;
    }
    ssum[g][f] = s; ssq[g][f] = q;
    __syncthreads();
    if (t < 64) {
        g_part[(b * 8 + slice) * 128 + t]      = ssum[0][t] + ssum[1][t] + ssum[2][t] + ssum[3][t];
        g_part[(b * 8 + slice) * 128 + 64 + t] = ssq[0][t]  + ssq[1][t]  + ssq[2][t]  + ssq[3][t];
    }
}

// ---------------- Kernel 1b: finish stats ----------------
__global__ __launch_bounds__(64) void kstat2(const int* __restrict__ nb)
{
    const int b = blockIdx.x, t = threadIdx.x;
    float S = 0.f, Q = 0.f;
    #pragma unroll
    for (int s = 0; s < 8; s++) {
        S += g_part[(b * 8 + s) * 128 + t];
        Q += g_part[(b * 8 + s) * 128 + 64 + t];
    }
    float cnt  = fmaxf((float)nb[b], 1.f);
    float mean = S / cnt;
    float var  = fmaxf(Q / cnt - mean * mean, 0.f);
    g_stats[b * 128 + t]      = mean;
    g_stats[b * 128 + 64 + t] = rsqrtf(var + 1e-5f);
}

// ---------------- Kernel 1c: normalize + fragment-major copies + sq ----------------
// CTA handles 8 consecutive nodes (one fragment row-block).
__global__ __launch_bounds__(256) void knorm2(const float* __restrict__ emb,
                                              const int* __restrict__ nb, int N)
{
    __shared__ float etile[8][65];   // emb rows
    __shared__ float ntile[8][65];   // embn rows

    const int t = threadIdx.x, w = t >> 5, lane = t & 31;
    const int row = blockIdx.x * 8 + w;     // global over B*N
    const int b = row / N, j = row - b * N;

    const float m0 = g_stats[b * 128 + lane];
    const float m1 = g_stats[b * 128 + lane + 32];
    const float r0 = g_stats[b * 128 + 64 + lane];
    const float r1 = g_stats[b * 128 + 64 + lane + 32];

    const float* E = emb + (size_t)row * 64;
    float e0 = E[lane], e1 = E[lane + 32];
    float m = (j < nb[b]) ? 1.f : 0.f;
    float n0 = (e0 - m0) * r0 * m;
    float n1 = (e1 - m1) * r1 * m;

    const int pf0 = phi(lane), pf1 = phi(lane + 32);
    g_Ep   [(size_t)row * 64 + pf0] = e0;
    g_Ep   [(size_t)row * 64 + pf1] = e1;
    g_embnP[(size_t)row * 64 + pf0] = n0;
    g_embnP[(size_t)row * 64 + pf1] = n1;
    etile[w][lane] = e0;  etile[w][lane + 32] = e1;
    ntile[w][lane] = n0;  ntile[w][lane + 32] = n1;

    float sq = e0 * e0 + e1 * e1;
    #pragma unroll
    for (int o = 16; o; o >>= 1) sq += __shfl_down_sync(0xffffffffu, sq, o);
    if (lane == 0) g_sq[row] = sq;

    __syncthreads();

    // coalesced fragment-major writes (CTA = one 8-row block)
    const int j0 = (blockIdx.x * 8) % N;
    const int b0 = (blockIdx.x * 8) / N;
    const int nbk = (j0 & 63) >> 3;
    const size_t tbase = ((size_t)(b0 * (N >> 6) + (j0 >> 6))) * 4096;

    #pragma unroll
    for (int it = 0; it < 2; it++) {
        const int idx = t + it * 256;     // 0..511
        const int seg = idx >> 6;         // block index 0..7
        const int sl  = idx & 63;         // float slot in 256B segment
        const int lp = sl >> 1, half = sl & 1;
        const int g = lp >> 2, q = lp & 3;
        // EjF: fragment (nb=nbk, ks=seg); rows j, k = f = seg*8 + half*4 + q
        g_EjF[tbase + (size_t)(nbk * 8 + seg) * 64 + sl] =
            __uint_as_float(f2tf(etile[g][seg * 8 + half * 4 + q]));
        // EnF: fragment (fb=seg, ks=nbk); rows f = seg*8 + g, k = j-local = half*4 + q
        g_EnF[tbase + (size_t)(seg * 8 + nbk) * 64 + sl] =
            __uint_as_float(f2tf(ntile[half * 4 + q][seg * 8 + g]));
    }
}

// ---------------- Kernel 2: fused Gram -> eltwise -> adj/deg -> SpMM ----------------
// 128 threads, 4 warps; warp w owns rows 16w..16w+15, full 64-j width.
#define SADJ 68
#define SMEM_EJF 0
#define SMEM_ENF 16384
#define SMEM_ADJ 32768
#define SMEM_SQ  (32768 + 64 * SADJ * 4)
#define SMEM_TOT (SMEM_SQ + 256)

__global__ __launch_bounds__(128, 4) void kadj(
    const float* __restrict__ adj_in,
    const int* __restrict__ nb, const float* __restrict__ sigma_p,
    const float* __restrict__ cw, float* __restrict__ adj_out, int N)
{
    extern __shared__ char smc[];
    const uint2* sEjF = (const uint2*)(smc + SMEM_EJF);   // 2048 uint2
    const uint2* sEnF = (const uint2*)(smc + SMEM_ENF);   // 2048 uint2
    float* sAdj = (float*)(smc + SMEM_ADJ);               // [64][SADJ]
    float* ssq  = (float*)(smc + SMEM_SQ);                // [64]

    const int b = blockIdx.y;
    const int ibase = blockIdx.x * 64;
    const int t = threadIdx.x;
    const int w = t >> 5, lane = t & 31;
    const int g = lane >> 2, tg = lane & 3;
    const int rowb = w * 16;
    const int p0 = (((2 * tg) & 3) << 1) | ((2 * tg) >> 2);
    const int p1 = (((2 * tg + 1) & 3) << 1) | ((2 * tg + 1) >> 2);

    const float inv_sigma = 1.0f / sigma_p[0];
    const float w0 = cw[0], w1 = cw[1];
    const int nbv = nb[b];

    const float* Ep   = g_Ep  + (size_t)b * N * 64;
    const float* SQ   = g_sq  + b * N;
    const float* Ain  = adj_in  + (size_t)b * N * N;
    float*       Aout = adj_out + (size_t)b * N * N;

    const uint32_t u_base = (uint32_t)__cvta_generic_to_shared(smc);

    const int gi0 = ibase + rowb + g;
    const int gi1 = gi0 + 8;

    auto stageAll = [&](int jt) {
        const size_t tIdx = (size_t)(b * (N >> 6) + (jt >> 6)) * 4096;
        const float* srcEj = g_EjF + tIdx;
        const float* srcEn = g_EnF + tIdx;
        #pragma unroll
        for (int k = 0; k < 8; k++) {
            const int c = t + k * 128;            // 0..1023 chunks
            cpa16(u_base + SMEM_EJF + c * 16, srcEj + c * 4);
            cpa16(u_base + SMEM_ENF + c * 16, srcEn + c * 4);
            const int r = c >> 4, c4 = (c & 15) << 2;
            cpa16(u_base + SMEM_ADJ + (r * SADJ + c4) * 4,
                  &Ain[(size_t)(ibase + r) * N + jt + c4]);
        }
        if (t < 16)
            cpa16(u_base + SMEM_SQ + t * 16, &SQ[jt + t * 4]);
    };

    stageAll(0);
    asm volatile("cp.async.commit_group;\n");

    // gemm1 A fragments (RNA tf32), persistent
    uint32_t aF[8][4];
    #pragma unroll
    for (int ks = 0; ks < 8; ks++) {
        float2 q0 = *(const float2*)&Ep[(size_t)gi0 * 64 + ks * 8 + 2 * tg];
        float2 q1 = *(const float2*)&Ep[(size_t)gi1 * 64 + ks * 8 + 2 * tg];
        aF[ks][0] = f2tf(q0.x);
        aF[ks][1] = f2tf(q1.x);
        aF[ks][2] = f2tf(q0.y);
        aF[ks][3] = f2tf(q1.y);
    }
    const float sqi0 = SQ[gi0];
    const float sqi1 = SQ[gi1];
    const float mi0 = (gi0 < nbv) ? 1.f : 0.f;
    const float mi1 = (gi1 < nbv) ? 1.f : 0.f;

    float opa[8][4];
    #pragma unroll
    for (int n = 0; n < 8; n++)
        #pragma unroll
        for (int k = 0; k < 4; k++) opa[n][k] = 0.f;
    float dg0 = 0.f, dg1 = 0.f;

    asm volatile("cp.async.wait_group 0;\n");
    __syncthreads();

    const int srcA = (lane & ~3) | (tg >> 1);
    const bool odd = tg & 1;

    for (int jt = 0; jt < N; jt += 64) {
        // ---- gemm1: S = emb_i . emb_j^T (fragment-major B, conflict-free) ----
        float S[8][4];
        #pragma unroll
        for (int n = 0; n < 8; n++)
            #pragma unroll
            for (int k = 0; k < 4; k++) S[n][k] = 0.f;

        #pragma unroll
        for (int nbk = 0; nbk < 8; nbk++) {
            #pragma unroll
            for (int ks = 0; ks < 8; ks++) {
                uint2 bv = sEjF[(nbk * 8 + ks) * 32 + lane];
                MMA_TF32(S[nbk], aF[ks][0], aF[ks][1], aF[ks][2], aF[ks][3], bv.x, bv.y);
            }
        }

        // ---- eltwise + in-register conversion to gemm2-A fragments ----
        #pragma unroll
        for (int nbk = 0; nbk < 8; nbk++) {
            const int jl = nbk * 8 + 2 * tg;
            const int gj = jt + jl;
            const float sqj0 = ssq[jl], sqj1 = ssq[jl + 1];
            const float mj0 = (gj     < nbv) ? 1.f : 0.f;
            const float mj1 = (gj + 1 < nbv) ? 1.f : 0.f;
            float2 a01 = *(const float2*)&sAdj[(rowb + g) * SADJ + jl];
            float2 a23 = *(const float2*)&sAdj[(rowb + g + 8) * SADJ + jl];

            float v00 = (w0 * a01.x + w1 * __expf(-fmaxf(sqi0 + sqj0 - 2.f * S[nbk][0], 0.f) * inv_sigma)) * (mi0 * mj0);
            float v01 = (w0 * a01.y + w1 * __expf(-fmaxf(sqi0 + sqj1 - 2.f * S[nbk][1], 0.f) * inv_sigma)) * (mi0 * mj1);
            float v10 = (w0 * a23.x + w1 * __expf(-fmaxf(sqi1 + sqj0 - 2.f * S[nbk][2], 0.f) * inv_sigma)) * (mi1 * mj0);
            float v11 = (w0 * a23.y + w1 * __expf(-fmaxf(sqi1 + sqj1 - 2.f * S[nbk][3], 0.f) * inv_sigma)) * (mi1 * mj1);

            dg0 += v00 + v01;
            dg1 += v10 + v11;

            *(float2*)&Aout[(size_t)gi0 * N + gj] = make_float2(v00, v01);
            *(float2*)&Aout[(size_t)gi1 * N + gj] = make_float2(v10, v11);

            // convert + shuffle accumulator layout -> A-fragment layout (in place)
            uint32_t c0 = f2tf(v00), c1 = f2tf(v01), c2 = f2tf(v10), c3 = f2tf(v11);
            uint32_t x0 = __shfl_sync(0xffffffffu, c0, srcA);
            uint32_t x1 = __shfl_sync(0xffffffffu, c1, srcA);
            uint32_t x2 = __shfl_sync(0xffffffffu, c2, srcA);
            uint32_t x3 = __shfl_sync(0xffffffffu, c3, srcA);
            uint32_t y0 = __shfl_sync(0xffffffffu, c0, srcA + 2);
            uint32_t y1 = __shfl_sync(0xffffffffu, c1, srcA + 2);
            uint32_t y2 = __shfl_sync(0xffffffffu, c2, srcA + 2);
            uint32_t y3 = __shfl_sync(0xffffffffu, c3, srcA + 2);
            S[nbk][0] = __uint_as_float(odd ? x1 : x0);
            S[nbk][1] = __uint_as_float(odd ? x3 : x2);
            S[nbk][2] = __uint_as_float(odd ? y1 : y0);
            S[nbk][3] = __uint_as_float(odd ? y3 : y2);
        }

        // ---- gemm2: op_adj += adj_tile @ embn (fragment-major B) ----
        #pragma unroll
        for (int fb = 0; fb < 8; fb++) {
            #pragma unroll
            for (int ks = 0; ks < 8; ks++) {
                uint2 bv = sEnF[(fb * 8 + ks) * 32 + lane];
                MMA_TF32(opa[fb],
                         __float_as_uint(S[ks][0]), __float_as_uint(S[ks][1]),
                         __float_as_uint(S[ks][2]), __float_as_uint(S[ks][3]),
                         bv.x, bv.y);
            }
        }

        if (jt + 64 < N) {
            __syncthreads();                          // all warps done with smem
            stageAll(jt + 64);
            asm volatile("cp.async.commit_group;\n");
            asm volatile("cp.async.wait_group 0;\n");
            __syncthreads();
        }
    }

    // ---- epilogue: deg (warp-local) + op_adj ----
    dg0 += __shfl_xor_sync(0xffffffffu, dg0, 1);
    dg0 += __shfl_xor_sync(0xffffffffu, dg0, 2);
    dg1 += __shfl_xor_sync(0xffffffffu, dg1, 1);
    dg1 += __shfl_xor_sync(0xffffffffu, dg1, 2);
    if (tg == 0) {
        g_deg[b * N + gi0] = dg0;
        g_deg[b * N + gi1] = dg1;
    }

    #pragma unroll
    for (int fb = 0; fb < 8; fb++) {
        const int cb = fb * 8;
        g_opadjP[(size_t)(b * N + gi0) * 64 + cb + p0] = opa[fb][0];
        g_opadjP[(size_t)(b * N + gi0) * 64 + cb + p1] = opa[fb][1];
        g_opadjP[(size_t)(b * N + gi1) * 64 + cb + p0] = opa[fb][2];
        g_opadjP[(size_t)(b * N + gi1) * 64 + cb + p1] = opa[fb][3];
    }
}

// ---------------- Kernel 3: fused 2-stage MLP, split-tf32 MMA (near-fp32) ----------------
#define SWP 136
#define SX  136

__global__ __launch_bounds__(256, 1) void knn(
    const float* __restrict__ embnP, const float* __restrict__ opadjP,
    const float* __restrict__ deg,   const float* __restrict__ Ep,
    const float* __restrict__ W1,    const float* __restrict__ b1,
    const float* __restrict__ W2,    const float* __restrict__ b2,
    float* __restrict__ out)
{
    extern __shared__ float smn[];
    uint32_t* sW1h = (uint32_t*)smn;
    uint32_t* sW1l = sW1h + 64 * SWP;
    uint32_t* sW2h = sW1l + 64 * SWP;
    uint32_t* sW2l = sW2h + 64 * SWP;
    float*    sx   = (float*)(sW2l + 64 * SWP);
    float*    sb1  = sx + 128 * SX;
    float*    sb2  = sb1 + 64;

    const int t = threadIdx.x;
    const int w = t >> 5, lane = t & 31;
    const int g = lane >> 2, tg = lane & 3;
    const int r0 = w * 16;
    const int node0 = blockIdx.x * 128;
    const int p0 = (((2 * tg) & 3) << 1) | ((2 * tg) >> 2);
    const int p1 = (((2 * tg + 1) & 3) << 1) | ((2 * tg + 1) >> 2);

    for (int idx = t; idx < 8192; idx += 256) {
        const int k = idx >> 6, n = idx & 63;
        const int pk = phi(k);
        uint32_t h, l;
        split_tf(W1[idx], h, l);
        sW1h[n * SWP + pk] = h; sW1l[n * SWP + pk] = l;
        split_tf(W2[idx], h, l);
        sW2h[n * SWP + pk] = h; sW2l[n * SWP + pk] = l;
    }
    if (t < 64) { sb1[t] = b1[t]; sb2[t] = b2[t]; }

    for (int idx = t; idx < 2048; idx += 256) {
        const int node = idx >> 4, c = (idx & 15) << 2;
        const float dgv = deg[node0 + node];
        float4 v = *(const float4*)&embnP[(size_t)(node0 + node) * 64 + c];
        v.x *= dgv; v.y *= dgv; v.z *= dgv; v.w *= dgv;
        *(float4*)&sx[node * SX + c] = v;
        *(float4*)&sx[node * SX + 64 + c] =
            *(const float4*)&opadjP[(size_t)(node0 + node) * 64 + c];
    }
    __syncthreads();

    float acc1[8][4];
    #pragma unroll
    for (int n = 0; n < 8; n++)
        #pragma unroll
        for (int k = 0; k < 4; k++) acc1[n][k] = 0.f;

    #pragma unroll
    for (int ks = 0; ks < 16; ks++) {
        float2 A0 = *(const float2*)&sx[(r0 + g)     * SX + ks * 8 + 2 * tg];
        float2 A1 = *(const float2*)&sx[(r0 + g + 8) * SX + ks * 8 + 2 * tg];
        uint32_t ah[4], al[4];
        split_tf(A0.x, ah[0], al[0]);
        split_tf(A1.x, ah[1], al[1]);
        split_tf(A0.y, ah[2], al[2]);
        split_tf(A1.y, ah[3], al[3]);
        #pragma unroll
        for (int nt = 0; nt < 8; nt++) {
            uint2 bh = *(const uint2*)&sW1h[(nt * 8 + g) * SWP + ks * 8 + 2 * tg];
            uint2 bl = *(const uint2*)&sW1l[(nt * 8 + g) * SWP + ks * 8 + 2 * tg];
            MMA_TF32(acc1[nt], ah[0], ah[1], ah[2], ah[3], bh.x, bh.y);
            MMA_TF32(acc1[nt], al[0], al[1], al[2], al[3], bh.x, bh.y);
            MMA_TF32(acc1[nt], ah[0], ah[1], ah[2], ah[3], bl.x, bl.y);
        }
    }
    __syncthreads();

    for (int idx = t; idx < 2048; idx += 256) {
        const int node = idx >> 4, c = (idx & 15) << 2;
        *(float4*)&sx[node * SX + c] = *(const float4*)&Ep[(size_t)(node0 + node) * 64 + c];
    }
    #pragma unroll
    for (int nt = 0; nt < 8; nt++) {
        const int f0 = nt * 8 + 2 * tg;
        const int base = 64 + nt * 8;
        sx[(r0 + g)     * SX + base + p0] = acc1[nt][0] + sb1[f0];
        sx[(r0 + g)     * SX + base + p1] = acc1[nt][1] + sb1[f0 + 1];
        sx[(r0 + g + 8) * SX + base + p0] = acc1[nt][2] + sb1[f0];
        sx[(r0 + g + 8) * SX + base + p1] = acc1[nt][3] + sb1[f0 + 1];
    }
    __syncthreads();

    float acc2[8][4];
    #pragma unroll
    for (int n = 0; n < 8; n++)
        #pragma unroll
        for (int k = 0; k < 4; k++) acc2[n][k] = 0.f;

    #pragma unroll
    for (int ks = 0; ks < 16; ks++) {
        float2 A0 = *(const float2*)&sx[(r0 + g)     * SX + ks * 8 + 2 * tg];
        float2 A1 = *(const float2*)&sx[(r0 + g + 8) * SX + ks * 8 + 2 * tg];
        uint32_t ah[4], al[4];
        split_tf(A0.x, ah[0], al[0]);
        split_tf(A1.x, ah[1], al[1]);
        split_tf(A0.y, ah[2], al[2]);
        split_tf(A1.y, ah[3], al[3]);
        #pragma unroll
        for (int nt = 0; nt < 8; nt++) {
            uint2 bh = *(const uint2*)&sW2h[(nt * 8 + g) * SWP + ks * 8 + 2 * tg];
            uint2 bl = *(const uint2*)&sW2l[(nt * 8 + g) * SWP + ks * 8 + 2 * tg];
            MMA_TF32(acc2[nt], ah[0], ah[1], ah[2], ah[3], bh.x, bh.y);
            MMA_TF32(acc2[nt], al[0], al[1], al[2], al[3], bh.x, bh.y);
            MMA_TF32(acc2[nt], ah[0], ah[1], ah[2], ah[3], bl.x, bl.y);
        }
    }

    #pragma unroll
    for (int nt = 0; nt < 8; nt++) {
        const int f0 = nt * 8 + 2 * tg;
        float o00 = fmaxf(acc2[nt][0] + sb2[f0],     0.f);
        float o01 = fmaxf(acc2[nt][1] + sb2[f0 + 1], 0.f);
        float o10 = fmaxf(acc2[nt][2] + sb2[f0],     0.f);
        float o11 = fmaxf(acc2[nt][3] + sb2[f0 + 1], 0.f);
        *(float2*)&out[(size_t)(node0 + r0 + g)     * 64 + f0] = make_float2(o00, o01);
        *(float2*)&out[(size_t)(node0 + r0 + g + 8) * 64 + f0] = make_float2(o10, o11);
    }
}

// ---------------- launch ----------------
extern "C" void kernel_launch(void* const* d_in, const int* in_sizes, int n_in,
                              void* d_out, int out_size)
{
    const float* emb_in = (const float*)d_in[0];
    const float* adj_in = (const float*)d_in[1];
    // d_in[2] adj_mask: unused (recomputed from batch_nb_nodes)
    const int*   nbp    = (const int*)d_in[3];
    const float* sigma  = (const float*)d_in[4];
    const float* cw     = (const float*)d_in[5];
    const float* convW  = (const float*)d_in[6];
    const float* convb  = (const float*)d_in[7];
    const float* nuW    = (const float*)d_in[8];
    const float* nub    = (const float*)d_in[9];

    const int B = in_sizes[3];
    const int N = in_sizes[0] / (B * 64);

    float* out_emb = (float*)d_out;                    // (B,N,64)
    float* out_adj = out_emb + (size_t)B * N * 64;     // (B,N,N)

    float *p_embnP, *p_opadjP, *p_deg, *p_Ep;
    cudaGetSymbolAddress((void**)&p_embnP,  g_embnP);
    cudaGetSymbolAddress((void**)&p_opadjP, g_opadjP);
    cudaGetSymbolAddress((void**)&p_deg,    g_deg);
    cudaGetSymbolAddress((void**)&p_Ep,     g_Ep);

    kstat1<<<dim3(B, 8), 256>>>(emb_in, N);
    kstat2<<<B, 64>>>(nbp);
    knorm2<<<(B * N) / 8, 256>>>(emb_in, nbp, N);

    cudaFuncSetAttribute(kadj, cudaFuncAttributeMaxDynamicSharedMemorySize, SMEM_TOT);
    kadj<<<dim3(N / 64, B), 128, SMEM_TOT>>>(adj_in, nbp, sigma, cw, out_adj, N);

    const size_t smemNN = (size_t)(4 * 64 * SWP + 128 * SX + 128) * sizeof(float);
    cudaFuncSetAttribute(knn, cudaFuncAttributeMaxDynamicSharedMemorySize, (int)smemNN);
    knn<<<(B * N) / 128, 256, smemNN>>>(p_embnP, p_opadjP, p_deg, p_Ep,
                                        convW, convb, nuW, nub, out_emb);
}